// round 11
// baseline (speedup 1.0000x reference)
#include <cuda_runtime.h>

#define NXD 1024
#define NYD 1024
#define BD  16
#define NP  (NXD * NYD)

// boundary: y in {0..3,1020..1023} all x (8192) + x in {0,1023}, y in [4,1019] (2032)
#define NBPTS   10224
#define NBTHR   (NBPTS * BD)          // 163584
#define NB_BLK  (NBTHR / 128)         // 1278 (exact)
#define NI_BLK  1024                  // 4 oct-col groups x 256 x-row groups

// ---- generic stencil helpers (boundary path) ----
__device__ __forceinline__ void gcoef1(int i, int N, int idx[3], float c[3], int& n) {
    if (i == 0)          { idx[0]=0;   idx[1]=1;   idx[2]=2;   c[0]=-1.5f; c[1]= 2.0f; c[2]=-0.5f; n=3; }
    else if (i == N - 1) { idx[0]=N-1; idx[1]=N-2; idx[2]=N-3; c[0]= 1.5f; c[1]=-2.0f; c[2]= 0.5f; n=3; }
    else                 { idx[0]=i-1; idx[1]=i+1; c[0]=-0.5f; c[1]=0.5f; n=2; }
}

__device__ __forceinline__ void gcoef2(int i, int N, int idx[4], float c[4], int& n) {
    if (i == 0)          { idx[0]=0;   idx[1]=1;   idx[2]=2;   idx[3]=3;   c[0]=2.0f; c[1]=-5.0f; c[2]=4.0f; c[3]=-1.0f; n=4; }
    else if (i == N - 1) { idx[0]=N-1; idx[1]=N-2; idx[2]=N-3; idx[3]=N-4; c[0]=2.0f; c[1]=-5.0f; c[2]=4.0f; c[3]=-1.0f; n=4; }
    else                 { idx[0]=i-1; idx[1]=i;   idx[2]=i+1; c[0]=1.0f; c[1]=-2.0f; c[2]=1.0f; n=3; }
}

__device__ __noinline__ float generic_df(const float* __restrict__ Fb,
                            const float* __restrict__ A0, const float* __restrict__ A1,
                            const float* __restrict__ B0, const float* __restrict__ B1,
                            const float* __restrict__ B2, int x, int y)
{
    int ix1[3]; float cx1[3]; int nx1;
    int iy1[3]; float cy1[3]; int ny1;
    gcoef1(x, NXD, ix1, cx1, nx1);
    gcoef1(y, NYD, iy1, cy1, ny1);

    int ix2[4]; float cx2[4]; int nx2;
    int iy2[4]; float cy2[4]; int ny2;
    gcoef2(x, NXD, ix2, cx2, nx2);
    gcoef2(y, NYD, iy2, cy2, ny2);

    float ga = 0.0f;
    #pragma unroll
    for (int j = 0; j < 3; ++j)
        if (j < nx1) { int k = ix1[j] * NYD + y; ga += cx1[j] * __ldg(&A0[k]) * __ldg(&Fb[k]); }
    #pragma unroll
    for (int j = 0; j < 3; ++j)
        if (j < ny1) { int k = x * NYD + iy1[j]; ga += cy1[j] * __ldg(&A1[k]) * __ldg(&Fb[k]); }

    float gb = 0.0f;
    #pragma unroll
    for (int j = 0; j < 4; ++j)
        if (j < nx2) { int k = ix2[j] * NYD + y; gb += cx2[j] * __ldg(&B0[k]) * __ldg(&Fb[k]); }
    #pragma unroll
    for (int j = 0; j < 4; ++j)
        if (j < ny2) { int k = x * NYD + iy2[j]; gb += cy2[j] * __ldg(&B1[k]) * __ldg(&Fb[k]); }

    float gc = 0.0f;
    #pragma unroll
    for (int j = 0; j < 3; ++j)
        if (j < nx1) {
            float acc = 0.0f;
            #pragma unroll
            for (int k = 0; k < 3; ++k)
                if (k < ny1) {
                    int idx = ix1[j] * NYD + iy1[k];
                    acc += cy1[k] * __ldg(&B2[idx]) * __ldg(&Fb[idx]);
                }
            gc += cx1[j] * acc;
        }
    return -ga + 0.5f * gb + gc;
}

// load 10-value row [base-1 .. base+8] with aligned vectors (base % 4 == 0)
__device__ __forceinline__ void load_row10(const float* __restrict__ P, int base, float d[10]) {
    float2 e0 = __ldg((const float2*)&P[base - 2]);
    float4 m0 = __ldg((const float4*)&P[base]);
    float4 m1 = __ldg((const float4*)&P[base + 4]);
    float2 e1 = __ldg((const float2*)&P[base + 8]);
    d[0]=e0.y; d[1]=m0.x; d[2]=m0.y; d[3]=m0.z; d[4]=m0.w;
    d[5]=m1.x; d[6]=m1.y; d[7]=m1.z; d[8]=m1.w; d[9]=e1.x;
}

// ================= fused kernel =================
// blocks [0, NB_BLK)             : boundary points (co-scheduled with interior)
// blocks [NB_BLK, NB_BLK+NI_BLK) : interior, 8 y-points/thread vector path
__global__ void __launch_bounds__(128, 4) fp2d_fused(
    const float* __restrict__ f,      // [B, NX, NY]
    const float* __restrict__ Agrid,  // [2, NX, NY]
    const float* __restrict__ Bgrid,  // [3, NX, NY]
    const float* __restrict__ dt,     // [B]
    float* __restrict__ out)          // [B, NX, NY]
{
    const float* __restrict__ A0 = Agrid;
    const float* __restrict__ A1 = Agrid + NP;
    const float* __restrict__ B0 = Bgrid;
    const float* __restrict__ B1 = Bgrid + NP;
    const float* __restrict__ B2 = Bgrid + 2 * NP;

    const int bid = blockIdx.x;

    if (bid < NB_BLK) {
        // ---------------- boundary path ----------------
        const int t = bid * 128 + threadIdx.x;     // < NBTHR exactly
        const int b   = t / NBPTS;
        const int idx = t - b * NBPTS;
        int x, y;
        if (idx < 8192) {
            x = idx >> 3;
            int r = idx & 7;
            y = (r < 4) ? r : (1016 + r);
        } else {
            int r = idx - 8192;
            x = (r & 1) ? 1023 : 0;
            y = 4 + (r >> 1);
        }
        const float* __restrict__ Fb = f + b * NP;
        const float df = generic_df(Fb, A0, A1, B0, B1, B2, x, y);
        const int k = x * NYD + y;
        float v = fmaf(df, __ldg(&dt[b]), __ldg(&Fb[k]));
        out[b * NP + k] = fmaxf(v, 0.0f);
        return;
    }

    // ---------------- interior path: 8 y-points per thread ----------------
    const int ib = bid - NB_BLK;
    const int bx = ib & 3;                     // 0..3   oct-column group
    const int by = ib >> 2;                    // 0..255 x-row group
    const int q  = bx * 32 + (threadIdx.x & 31);       // oct index, want [0,126]
    const int x  = 1 + by * 4 + (threadIdx.x >> 5);    // want [1,1022]
    if (q > 126 || x > 1022) return;
    const int y0 = 4 + q * 8;                  // y0 in [4,1012], 16B aligned

    const int bm = (x - 1) * NYD + y0;
    const int bc =  x      * NYD + y0;
    const int bp = (x + 1) * NYD + y0;

    // ---- batch-invariant grid rows ----
    float b2m[10], b2p[10], a1v[10], b1v[10];
    load_row10(B2, bm, b2m);
    load_row10(B2, bp, b2p);
    load_row10(A1, bc, a1v);
    load_row10(B1, bc, b1v);

    float a0m[8], a0p[8], b0m[8], b0c[8], b0p[8];
    {
        float4 t0, t1;
        t0 = __ldg((const float4*)&A0[bm]); t1 = __ldg((const float4*)&A0[bm + 4]);
        a0m[0]=t0.x;a0m[1]=t0.y;a0m[2]=t0.z;a0m[3]=t0.w;a0m[4]=t1.x;a0m[5]=t1.y;a0m[6]=t1.z;a0m[7]=t1.w;
        t0 = __ldg((const float4*)&A0[bp]); t1 = __ldg((const float4*)&A0[bp + 4]);
        a0p[0]=t0.x;a0p[1]=t0.y;a0p[2]=t0.z;a0p[3]=t0.w;a0p[4]=t1.x;a0p[5]=t1.y;a0p[6]=t1.z;a0p[7]=t1.w;
        t0 = __ldg((const float4*)&B0[bm]); t1 = __ldg((const float4*)&B0[bm + 4]);
        b0m[0]=t0.x;b0m[1]=t0.y;b0m[2]=t0.z;b0m[3]=t0.w;b0m[4]=t1.x;b0m[5]=t1.y;b0m[6]=t1.z;b0m[7]=t1.w;
        t0 = __ldg((const float4*)&B0[bc]); t1 = __ldg((const float4*)&B0[bc + 4]);
        b0c[0]=t0.x;b0c[1]=t0.y;b0c[2]=t0.z;b0c[3]=t0.w;b0c[4]=t1.x;b0c[5]=t1.y;b0c[6]=t1.z;b0c[7]=t1.w;
        t0 = __ldg((const float4*)&B0[bp]); t1 = __ldg((const float4*)&B0[bp + 4]);
        b0p[0]=t0.x;b0p[1]=t0.y;b0p[2]=t0.z;b0p[3]=t0.w;b0p[4]=t1.x;b0p[5]=t1.y;b0p[6]=t1.z;b0p[7]=t1.w;
    }

    // ---- fold into 9 weights per point (72 regs) ----
    float wmm[8], wm0[8], wmp[8], w0m[8], w00[8], w0p[8], wpm[8], wp0[8], wpp[8];
    #pragma unroll
    for (int s = 0; s < 8; ++s) {
        wmm[s] =  0.25f * b2m[s];
        wmp[s] = -0.25f * b2m[s + 2];
        wpm[s] = -0.25f * b2p[s];
        wpp[s] =  0.25f * b2p[s + 2];
        w0m[s] =  0.5f * (a1v[s] + b1v[s]);
        w0p[s] =  0.5f * (b1v[s + 2] - a1v[s + 2]);
        wm0[s] =  0.5f * (a0m[s] + b0m[s]);
        wp0[s] =  0.5f * (b0p[s] - a0p[s]);
        w00[s] = -(b0c[s] + b1v[s + 1]);
    }

    // ---- batch loop: 12 vector loads -> 72 FMA -> 2x STG.128 ----
    const float* __restrict__ Fb = f;
    float* __restrict__ Ob = out + bc;
    for (int b = 0; b < BD; ++b, Fb += NP, Ob += NP) {
        const float dtb = __ldg(&dt[b]);

        float dm[10], dc[10], dp[10];
        load_row10(Fb, bm, dm);
        load_row10(Fb, bc, dc);
        load_row10(Fb, bp, dp);

        float o[8];
        #pragma unroll
        for (int s = 0; s < 8; ++s) {
            float df;
            df = wmm[s] * dm[s];
            df = fmaf(wm0[s], dm[s + 1], df);
            df = fmaf(wmp[s], dm[s + 2], df);
            df = fmaf(w0m[s], dc[s],     df);
            df = fmaf(w00[s], dc[s + 1], df);
            df = fmaf(w0p[s], dc[s + 2], df);
            df = fmaf(wpm[s], dp[s],     df);
            df = fmaf(wp0[s], dp[s + 1], df);
            df = fmaf(wpp[s], dp[s + 2], df);
            o[s] = fmaxf(fmaf(df, dtb, dc[s + 1]), 0.0f);
        }
        *(float4*)Ob       = make_float4(o[0], o[1], o[2], o[3]);
        *(float4*)(Ob + 4) = make_float4(o[4], o[5], o[6], o[7]);
    }
}

extern "C" void kernel_launch(void* const* d_in, const int* in_sizes, int n_in,
                              void* d_out, int out_size) {
    const float* f  = (const float*)d_in[0];
    const float* Ag = (const float*)d_in[1];
    const float* Bg = (const float*)d_in[2];
    const float* dt = (const float*)d_in[3];
    float* out = (float*)d_out;

    fp2d_fused<<<NB_BLK + NI_BLK, 128>>>(f, Ag, Bg, dt, out);
}

// round 12
// speedup vs baseline: 1.0683x; 1.0683x over previous
#include <cuda_runtime.h>

#define NXD 1024
#define NYD 1024
#define BD  16
#define NP  (NXD * NYD)

// boundary: y in {0..3,1020..1023} all x (8192) + x in {0,1023}, y in [4,1019] (2032)
#define NBPTS   10224
#define NBTHR   (NBPTS * BD)          // 163584
#define NB_BLK  (NBTHR / 128)         // 1278 (exact)
#define NI_BLK  1024                  // 8 quad-col groups x 128 x-pair groups

// ---- generic stencil helpers (boundary path) ----
__device__ __forceinline__ void gcoef1(int i, int N, int idx[3], float c[3], int& n) {
    if (i == 0)          { idx[0]=0;   idx[1]=1;   idx[2]=2;   c[0]=-1.5f; c[1]= 2.0f; c[2]=-0.5f; n=3; }
    else if (i == N - 1) { idx[0]=N-1; idx[1]=N-2; idx[2]=N-3; c[0]= 1.5f; c[1]=-2.0f; c[2]= 0.5f; n=3; }
    else                 { idx[0]=i-1; idx[1]=i+1; c[0]=-0.5f; c[1]=0.5f; n=2; }
}

__device__ __forceinline__ void gcoef2(int i, int N, int idx[4], float c[4], int& n) {
    if (i == 0)          { idx[0]=0;   idx[1]=1;   idx[2]=2;   idx[3]=3;   c[0]=2.0f; c[1]=-5.0f; c[2]=4.0f; c[3]=-1.0f; n=4; }
    else if (i == N - 1) { idx[0]=N-1; idx[1]=N-2; idx[2]=N-3; idx[3]=N-4; c[0]=2.0f; c[1]=-5.0f; c[2]=4.0f; c[3]=-1.0f; n=4; }
    else                 { idx[0]=i-1; idx[1]=i;   idx[2]=i+1; c[0]=1.0f; c[1]=-2.0f; c[2]=1.0f; n=3; }
}

__device__ __noinline__ float generic_df(const float* __restrict__ Fb,
                            const float* __restrict__ A0, const float* __restrict__ A1,
                            const float* __restrict__ B0, const float* __restrict__ B1,
                            const float* __restrict__ B2, int x, int y)
{
    int ix1[3]; float cx1[3]; int nx1;
    int iy1[3]; float cy1[3]; int ny1;
    gcoef1(x, NXD, ix1, cx1, nx1);
    gcoef1(y, NYD, iy1, cy1, ny1);

    int ix2[4]; float cx2[4]; int nx2;
    int iy2[4]; float cy2[4]; int ny2;
    gcoef2(x, NXD, ix2, cx2, nx2);
    gcoef2(y, NYD, iy2, cy2, ny2);

    float ga = 0.0f;
    #pragma unroll
    for (int j = 0; j < 3; ++j)
        if (j < nx1) { int k = ix1[j] * NYD + y; ga += cx1[j] * __ldg(&A0[k]) * __ldg(&Fb[k]); }
    #pragma unroll
    for (int j = 0; j < 3; ++j)
        if (j < ny1) { int k = x * NYD + iy1[j]; ga += cy1[j] * __ldg(&A1[k]) * __ldg(&Fb[k]); }

    float gb = 0.0f;
    #pragma unroll
    for (int j = 0; j < 4; ++j)
        if (j < nx2) { int k = ix2[j] * NYD + y; gb += cx2[j] * __ldg(&B0[k]) * __ldg(&Fb[k]); }
    #pragma unroll
    for (int j = 0; j < 4; ++j)
        if (j < ny2) { int k = x * NYD + iy2[j]; gb += cy2[j] * __ldg(&B1[k]) * __ldg(&Fb[k]); }

    float gc = 0.0f;
    #pragma unroll
    for (int j = 0; j < 3; ++j)
        if (j < nx1) {
            float acc = 0.0f;
            #pragma unroll
            for (int k = 0; k < 3; ++k)
                if (k < ny1) {
                    int idx = ix1[j] * NYD + iy1[k];
                    acc += cy1[k] * __ldg(&B2[idx]) * __ldg(&Fb[idx]);
                }
            gc += cx1[j] * acc;
        }
    return -ga + 0.5f * gb + gc;
}

// 6-value row [base-1 .. base+4], base % 4 == 0, lane stride 16B
__device__ __forceinline__ void load_row6(const float* __restrict__ P, int base, float d[6]) {
    float2 e0 = __ldg((const float2*)&P[base - 2]);
    float4 m  = __ldg((const float4*)&P[base]);
    float2 e1 = __ldg((const float2*)&P[base + 4]);
    d[0]=e0.y; d[1]=m.x; d[2]=m.y; d[3]=m.z; d[4]=m.w; d[5]=e1.x;
}

// ================= fused kernel =================
// blocks [0, NB_BLK)             : boundary points
// blocks [NB_BLK, NB_BLK+NI_BLK) : interior, 2 x-rows x 4 y-points per thread
__global__ void __launch_bounds__(128, 4) fp2d_fused(
    const float* __restrict__ f,      // [B, NX, NY]
    const float* __restrict__ Agrid,  // [2, NX, NY]
    const float* __restrict__ Bgrid,  // [3, NX, NY]
    const float* __restrict__ dt,     // [B]
    float* __restrict__ out)          // [B, NX, NY]
{
    const float* __restrict__ A0 = Agrid;
    const float* __restrict__ A1 = Agrid + NP;
    const float* __restrict__ B0 = Bgrid;
    const float* __restrict__ B1 = Bgrid + NP;
    const float* __restrict__ B2 = Bgrid + 2 * NP;

    const int bid = blockIdx.x;

    if (bid < NB_BLK) {
        // ---------------- boundary path ----------------
        const int t = bid * 128 + threadIdx.x;     // < NBTHR exactly
        const int b   = t / NBPTS;
        const int idx = t - b * NBPTS;
        int x, y;
        if (idx < 8192) {
            x = idx >> 3;
            int r = idx & 7;
            y = (r < 4) ? r : (1016 + r);
        } else {
            int r = idx - 8192;
            x = (r & 1) ? 1023 : 0;
            y = 4 + (r >> 1);
        }
        const float* __restrict__ Fb = f + b * NP;
        const float df = generic_df(Fb, A0, A1, B0, B1, B2, x, y);
        const int k = x * NYD + y;
        float v = fmaf(df, __ldg(&dt[b]), __ldg(&Fb[k]));
        out[b * NP + k] = fmaxf(v, 0.0f);
        return;
    }

    // ---------------- interior path: 2 x-rows x 4 y-points ----------------
    const int ib = bid - NB_BLK;
    const int bx = ib & 7;                    // 0..7   quad-column group
    const int by = ib >> 3;                   // 0..127 x-pair group
    const int q  = 1 + bx * 32 + (threadIdx.x & 31);   // quad index, want [1,254]
    const int p  = by * 4 + (threadIdx.x >> 5);        // x-pair index, want [0,510]
    if (q > 254 || p > 510) return;
    const int x0 = 1 + 2 * p;                 // x0 in [1,1021]; rows x0, x0+1
    const int y0 = q * 4;                     // y0 in [4,1016], 16B aligned

    // row bases: R0=x0-1, R1=x0, R2=x0+1, R3=x0+2
    const int b0_ = (x0 - 1) * NYD + y0;
    const int b1_ =  x0      * NYD + y0;
    const int b2_ = (x0 + 1) * NYD + y0;
    const int b3_ = (x0 + 2) * NYD + y0;

    // ---- batch-invariant grid rows ----
    float b2r0[6], b2r1[6], b2r2[6], b2r3[6], a1r1[6], a1r2[6], b1r1[6], b1r2[6];
    load_row6(B2, b0_, b2r0);
    load_row6(B2, b1_, b2r1);
    load_row6(B2, b2_, b2r2);
    load_row6(B2, b3_, b2r3);
    load_row6(A1, b1_, a1r1);
    load_row6(A1, b2_, a1r2);
    load_row6(B1, b1_, b1r1);
    load_row6(B1, b2_, b1r2);

    const float4 a0r0 = __ldg((const float4*)&A0[b0_]);
    const float4 a0r1 = __ldg((const float4*)&A0[b1_]);
    const float4 a0r2 = __ldg((const float4*)&A0[b2_]);
    const float4 a0r3 = __ldg((const float4*)&A0[b3_]);
    const float4 b0r0 = __ldg((const float4*)&B0[b0_]);
    const float4 b0r1 = __ldg((const float4*)&B0[b1_]);
    const float4 b0r2 = __ldg((const float4*)&B0[b2_]);
    const float4 b0r3 = __ldg((const float4*)&B0[b3_]);

    // ---- fold into 9 weights per point, 2 x-rows ----
    float wmm[2][4], wm0[2][4], wmp[2][4], w0m[2][4], w00[2][4], w0p[2][4],
          wpm[2][4], wp0[2][4], wpp[2][4];
    {
        const float a0m_[2][4] = {{a0r0.x,a0r0.y,a0r0.z,a0r0.w},{a0r1.x,a0r1.y,a0r1.z,a0r1.w}};
        const float a0p_[2][4] = {{a0r2.x,a0r2.y,a0r2.z,a0r2.w},{a0r3.x,a0r3.y,a0r3.z,a0r3.w}};
        const float b0m_[2][4] = {{b0r0.x,b0r0.y,b0r0.z,b0r0.w},{b0r1.x,b0r1.y,b0r1.z,b0r1.w}};
        const float b0c_[2][4] = {{b0r1.x,b0r1.y,b0r1.z,b0r1.w},{b0r2.x,b0r2.y,b0r2.z,b0r2.w}};
        const float b0p_[2][4] = {{b0r2.x,b0r2.y,b0r2.z,b0r2.w},{b0r3.x,b0r3.y,b0r3.z,b0r3.w}};
        const float* b2m_[2] = {b2r0, b2r1};
        const float* b2p_[2] = {b2r2, b2r3};
        const float* a1c_[2] = {a1r1, a1r2};
        const float* b1c_[2] = {b1r1, b1r2};
        #pragma unroll
        for (int r = 0; r < 2; ++r) {
            #pragma unroll
            for (int s = 0; s < 4; ++s) {
                wmm[r][s] =  0.25f * b2m_[r][s];
                wmp[r][s] = -0.25f * b2m_[r][s + 2];
                wpm[r][s] = -0.25f * b2p_[r][s];
                wpp[r][s] =  0.25f * b2p_[r][s + 2];
                w0m[r][s] =  0.5f * (a1c_[r][s] + b1c_[r][s]);
                w0p[r][s] =  0.5f * (b1c_[r][s + 2] - a1c_[r][s + 2]);
                wm0[r][s] =  0.5f * (a0m_[r][s] + b0m_[r][s]);
                wp0[r][s] =  0.5f * (b0p_[r][s] - a0p_[r][s]);
                w00[r][s] = -(b0c_[r][s] + b1c_[r][s + 1]);
            }
        }
    }

    // ---- batch loop: 4 row-loads (12 LDG) -> 72 FMA -> 2x STG.128 ----
    const float* __restrict__ Fb = f;
    float* __restrict__ O1 = out + b1_;
    float* __restrict__ O2 = out + b2_;
    for (int b = 0; b < BD; ++b, Fb += NP, O1 += NP, O2 += NP) {
        const float dtb = __ldg(&dt[b]);

        float d0[6], d1[6], d2[6], d3[6];
        load_row6(Fb, b0_, d0);
        load_row6(Fb, b1_, d1);
        load_row6(Fb, b2_, d2);
        load_row6(Fb, b3_, d3);

        float o0[4], o1[4];
        #pragma unroll
        for (int s = 0; s < 4; ++s) {
            float df;
            // x-row 0: rows d0 (m), d1 (c), d2 (p)
            df = wmm[0][s] * d0[s];
            df = fmaf(wm0[0][s], d0[s + 1], df);
            df = fmaf(wmp[0][s], d0[s + 2], df);
            df = fmaf(w0m[0][s], d1[s],     df);
            df = fmaf(w00[0][s], d1[s + 1], df);
            df = fmaf(w0p[0][s], d1[s + 2], df);
            df = fmaf(wpm[0][s], d2[s],     df);
            df = fmaf(wp0[0][s], d2[s + 1], df);
            df = fmaf(wpp[0][s], d2[s + 2], df);
            o0[s] = fmaxf(fmaf(df, dtb, d1[s + 1]), 0.0f);
            // x-row 1: rows d1 (m), d2 (c), d3 (p)
            df = wmm[1][s] * d1[s];
            df = fmaf(wm0[1][s], d1[s + 1], df);
            df = fmaf(wmp[1][s], d1[s + 2], df);
            df = fmaf(w0m[1][s], d2[s],     df);
            df = fmaf(w00[1][s], d2[s + 1], df);
            df = fmaf(w0p[1][s], d2[s + 2], df);
            df = fmaf(wpm[1][s], d3[s],     df);
            df = fmaf(wp0[1][s], d3[s + 1], df);
            df = fmaf(wpp[1][s], d3[s + 2], df);
            o1[s] = fmaxf(fmaf(df, dtb, d2[s + 1]), 0.0f);
        }
        *(float4*)O1 = make_float4(o0[0], o0[1], o0[2], o0[3]);
        *(float4*)O2 = make_float4(o1[0], o1[1], o1[2], o1[3]);
    }
}

extern "C" void kernel_launch(void* const* d_in, const int* in_sizes, int n_in,
                              void* d_out, int out_size) {
    const float* f  = (const float*)d_in[0];
    const float* Ag = (const float*)d_in[1];
    const float* Bg = (const float*)d_in[2];
    const float* dt = (const float*)d_in[3];
    float* out = (float*)d_out;

    fp2d_fused<<<NB_BLK + NI_BLK, 128>>>(f, Ag, Bg, dt, out);
}

// round 13
// speedup vs baseline: 1.1633x; 1.0890x over previous
#include <cuda_runtime.h>

#define NXD 1024
#define NYD 1024
#define BD  16
#define NP  (NXD * NYD)

// boundary: y in {0..3,1020..1023} all x (8192) + x in {0,1023}, y in [4,1019] (2032)
#define NBPTS   10224
#define NB_BLK  80                    // ceil(10224/128); each thread loops 16 batches
#define NI_BLK  1024                  // 8 quad-col groups x 128 x-pair groups

// ---- generic stencil helpers (boundary path) ----
__device__ __forceinline__ void gcoef1(int i, int N, int idx[3], float c[3], int& n) {
    if (i == 0)          { idx[0]=0;   idx[1]=1;   idx[2]=2;   c[0]=-1.5f; c[1]= 2.0f; c[2]=-0.5f; n=3; }
    else if (i == N - 1) { idx[0]=N-1; idx[1]=N-2; idx[2]=N-3; c[0]= 1.5f; c[1]=-2.0f; c[2]= 0.5f; n=3; }
    else                 { idx[0]=i-1; idx[1]=i+1; c[0]=-0.5f; c[1]=0.5f; n=2; }
}

__device__ __forceinline__ void gcoef2(int i, int N, int idx[4], float c[4], int& n) {
    if (i == 0)          { idx[0]=0;   idx[1]=1;   idx[2]=2;   idx[3]=3;   c[0]=2.0f; c[1]=-5.0f; c[2]=4.0f; c[3]=-1.0f; n=4; }
    else if (i == N - 1) { idx[0]=N-1; idx[1]=N-2; idx[2]=N-3; idx[3]=N-4; c[0]=2.0f; c[1]=-5.0f; c[2]=4.0f; c[3]=-1.0f; n=4; }
    else                 { idx[0]=i-1; idx[1]=i;   idx[2]=i+1; c[0]=1.0f; c[1]=-2.0f; c[2]=1.0f; n=3; }
}

__device__ __noinline__ float generic_df(const float* __restrict__ Fb,
                            const float* __restrict__ A0, const float* __restrict__ A1,
                            const float* __restrict__ B0, const float* __restrict__ B1,
                            const float* __restrict__ B2, int x, int y)
{
    int ix1[3]; float cx1[3]; int nx1;
    int iy1[3]; float cy1[3]; int ny1;
    gcoef1(x, NXD, ix1, cx1, nx1);
    gcoef1(y, NYD, iy1, cy1, ny1);

    int ix2[4]; float cx2[4]; int nx2;
    int iy2[4]; float cy2[4]; int ny2;
    gcoef2(x, NXD, ix2, cx2, nx2);
    gcoef2(y, NYD, iy2, cy2, ny2);

    float ga = 0.0f;
    #pragma unroll
    for (int j = 0; j < 3; ++j)
        if (j < nx1) { int k = ix1[j] * NYD + y; ga += cx1[j] * __ldg(&A0[k]) * __ldg(&Fb[k]); }
    #pragma unroll
    for (int j = 0; j < 3; ++j)
        if (j < ny1) { int k = x * NYD + iy1[j]; ga += cy1[j] * __ldg(&A1[k]) * __ldg(&Fb[k]); }

    float gb = 0.0f;
    #pragma unroll
    for (int j = 0; j < 4; ++j)
        if (j < nx2) { int k = ix2[j] * NYD + y; gb += cx2[j] * __ldg(&B0[k]) * __ldg(&Fb[k]); }
    #pragma unroll
    for (int j = 0; j < 4; ++j)
        if (j < ny2) { int k = x * NYD + iy2[j]; gb += cy2[j] * __ldg(&B1[k]) * __ldg(&Fb[k]); }

    float gc = 0.0f;
    #pragma unroll
    for (int j = 0; j < 3; ++j)
        if (j < nx1) {
            float acc = 0.0f;
            #pragma unroll
            for (int k = 0; k < 3; ++k)
                if (k < ny1) {
                    int idx = ix1[j] * NYD + iy1[k];
                    acc += cy1[k] * __ldg(&B2[idx]) * __ldg(&Fb[idx]);
                }
            gc += cx1[j] * acc;
        }
    return -ga + 0.5f * gb + gc;
}

// 6-value row [base-1 .. base+4], base % 4 == 0, lane stride 16B
__device__ __forceinline__ void load_row6(const float* __restrict__ P, int base, float d[6]) {
    float2 e0 = __ldg((const float2*)&P[base - 2]);
    float4 m  = __ldg((const float4*)&P[base]);
    float2 e1 = __ldg((const float2*)&P[base + 4]);
    d[0]=e0.y; d[1]=m.x; d[2]=m.y; d[3]=m.z; d[4]=m.w; d[5]=e1.x;
}

// ================= fused kernel =================
// blocks [0, NB_BLK)             : boundary points (each thread loops 16 batches)
// blocks [NB_BLK, NB_BLK+NI_BLK) : interior, 2x-rows x 4y patch, batch-paired loop
__global__ void __launch_bounds__(128, 3) fp2d_fused(
    const float* __restrict__ f,      // [B, NX, NY]
    const float* __restrict__ Agrid,  // [2, NX, NY]
    const float* __restrict__ Bgrid,  // [3, NX, NY]
    const float* __restrict__ dt,     // [B]
    float* __restrict__ out)          // [B, NX, NY]
{
    const float* __restrict__ A0 = Agrid;
    const float* __restrict__ A1 = Agrid + NP;
    const float* __restrict__ B0 = Bgrid;
    const float* __restrict__ B1 = Bgrid + NP;
    const float* __restrict__ B2 = Bgrid + 2 * NP;

    const int bid = blockIdx.x;

    if (bid < NB_BLK) {
        // ---------------- boundary path: one point, 16 batches ----------------
        const int idx = bid * 128 + threadIdx.x;
        if (idx >= NBPTS) return;
        int x, y;
        if (idx < 8192) {
            x = idx >> 3;
            int r = idx & 7;
            y = (r < 4) ? r : (1016 + r);
        } else {
            int r = idx - 8192;
            x = (r & 1) ? 1023 : 0;
            y = 4 + (r >> 1);
        }
        const int k = x * NYD + y;
        const float* __restrict__ Fb = f;
        float* __restrict__ Ob = out + k;
        for (int b = 0; b < BD; ++b, Fb += NP, Ob += NP) {
            const float df = generic_df(Fb, A0, A1, B0, B1, B2, x, y);
            float v = fmaf(df, __ldg(&dt[b]), __ldg(&Fb[k]));
            *Ob = fmaxf(v, 0.0f);
        }
        return;
    }

    // ---------------- interior path: 2 x-rows x 4 y-points, 2 batches/iter ----------------
    const int ib = bid - NB_BLK;
    const int bx = ib & 7;                    // 0..7   quad-column group
    const int by = ib >> 3;                   // 0..127 x-pair group
    const int q  = 1 + bx * 32 + (threadIdx.x & 31);   // quad index, want [1,254]
    const int p  = by * 4 + (threadIdx.x >> 5);        // x-pair index, want [0,510]
    if (q > 254 || p > 510) return;
    const int x0 = 1 + 2 * p;                 // rows x0, x0+1
    const int y0 = q * 4;

    const int b0_ = (x0 - 1) * NYD + y0;
    const int b1_ =  x0      * NYD + y0;
    const int b2_ = (x0 + 1) * NYD + y0;
    const int b3_ = (x0 + 2) * NYD + y0;

    // ---- batch-invariant grid rows ----
    float b2r0[6], b2r1[6], b2r2[6], b2r3[6], a1r1[6], a1r2[6], b1r1[6], b1r2[6];
    load_row6(B2, b0_, b2r0);
    load_row6(B2, b1_, b2r1);
    load_row6(B2, b2_, b2r2);
    load_row6(B2, b3_, b2r3);
    load_row6(A1, b1_, a1r1);
    load_row6(A1, b2_, a1r2);
    load_row6(B1, b1_, b1r1);
    load_row6(B1, b2_, b1r2);

    const float4 a0r0 = __ldg((const float4*)&A0[b0_]);
    const float4 a0r1 = __ldg((const float4*)&A0[b1_]);
    const float4 a0r2 = __ldg((const float4*)&A0[b2_]);
    const float4 a0r3 = __ldg((const float4*)&A0[b3_]);
    const float4 b0r0 = __ldg((const float4*)&B0[b0_]);
    const float4 b0r1 = __ldg((const float4*)&B0[b1_]);
    const float4 b0r2 = __ldg((const float4*)&B0[b2_]);
    const float4 b0r3 = __ldg((const float4*)&B0[b3_]);

    // ---- fold into 9 weights per point, 2 x-rows ----
    float wmm[2][4], wm0[2][4], wmp[2][4], w0m[2][4], w00[2][4], w0p[2][4],
          wpm[2][4], wp0[2][4], wpp[2][4];
    {
        const float a0m_[2][4] = {{a0r0.x,a0r0.y,a0r0.z,a0r0.w},{a0r1.x,a0r1.y,a0r1.z,a0r1.w}};
        const float a0p_[2][4] = {{a0r2.x,a0r2.y,a0r2.z,a0r2.w},{a0r3.x,a0r3.y,a0r3.z,a0r3.w}};
        const float b0m_[2][4] = {{b0r0.x,b0r0.y,b0r0.z,b0r0.w},{b0r1.x,b0r1.y,b0r1.z,b0r1.w}};
        const float b0c_[2][4] = {{b0r1.x,b0r1.y,b0r1.z,b0r1.w},{b0r2.x,b0r2.y,b0r2.z,b0r2.w}};
        const float b0p_[2][4] = {{b0r2.x,b0r2.y,b0r2.z,b0r2.w},{b0r3.x,b0r3.y,b0r3.z,b0r3.w}};
        const float* b2m_[2] = {b2r0, b2r1};
        const float* b2p_[2] = {b2r2, b2r3};
        const float* a1c_[2] = {a1r1, a1r2};
        const float* b1c_[2] = {b1r1, b1r2};
        #pragma unroll
        for (int r = 0; r < 2; ++r) {
            #pragma unroll
            for (int s = 0; s < 4; ++s) {
                wmm[r][s] =  0.25f * b2m_[r][s];
                wmp[r][s] = -0.25f * b2m_[r][s + 2];
                wpm[r][s] = -0.25f * b2p_[r][s];
                wpp[r][s] =  0.25f * b2p_[r][s + 2];
                w0m[r][s] =  0.5f * (a1c_[r][s] + b1c_[r][s]);
                w0p[r][s] =  0.5f * (b1c_[r][s + 2] - a1c_[r][s + 2]);
                wm0[r][s] =  0.5f * (a0m_[r][s] + b0m_[r][s]);
                wp0[r][s] =  0.5f * (b0p_[r][s] - a0p_[r][s]);
                w00[r][s] = -(b0c_[r][s] + b1c_[r][s + 1]);
            }
        }
    }

    // ---- batch loop: 2 independent batches per iter (b, b+8) -> 24 loads in flight ----
    const float* __restrict__ FbA = f;
    const float* __restrict__ FbB = f + 8 * NP;
    float* __restrict__ O1A = out + b1_;
    float* __restrict__ O1B = out + b1_ + 8 * NP;
    for (int b = 0; b < 8; ++b, FbA += NP, FbB += NP, O1A += NP, O1B += NP) {
        const float dtA = __ldg(&dt[b]);
        const float dtB = __ldg(&dt[b + 8]);

        float dA0[6], dA1[6], dA2[6], dA3[6];
        float dB0[6], dB1[6], dB2[6], dB3[6];
        load_row6(FbA, b0_, dA0);
        load_row6(FbA, b1_, dA1);
        load_row6(FbA, b2_, dA2);
        load_row6(FbA, b3_, dA3);
        load_row6(FbB, b0_, dB0);
        load_row6(FbB, b1_, dB1);
        load_row6(FbB, b2_, dB2);
        load_row6(FbB, b3_, dB3);

        float oA0[4], oA1[4], oB0[4], oB1[4];
        #pragma unroll
        for (int s = 0; s < 4; ++s) {
            float df;
            // batch A, x-row 0
            df = wmm[0][s] * dA0[s];
            df = fmaf(wm0[0][s], dA0[s + 1], df);
            df = fmaf(wmp[0][s], dA0[s + 2], df);
            df = fmaf(w0m[0][s], dA1[s],     df);
            df = fmaf(w00[0][s], dA1[s + 1], df);
            df = fmaf(w0p[0][s], dA1[s + 2], df);
            df = fmaf(wpm[0][s], dA2[s],     df);
            df = fmaf(wp0[0][s], dA2[s + 1], df);
            df = fmaf(wpp[0][s], dA2[s + 2], df);
            oA0[s] = fmaxf(fmaf(df, dtA, dA1[s + 1]), 0.0f);
            // batch A, x-row 1
            df = wmm[1][s] * dA1[s];
            df = fmaf(wm0[1][s], dA1[s + 1], df);
            df = fmaf(wmp[1][s], dA1[s + 2], df);
            df = fmaf(w0m[1][s], dA2[s],     df);
            df = fmaf(w00[1][s], dA2[s + 1], df);
            df = fmaf(w0p[1][s], dA2[s + 2], df);
            df = fmaf(wpm[1][s], dA3[s],     df);
            df = fmaf(wp0[1][s], dA3[s + 1], df);
            df = fmaf(wpp[1][s], dA3[s + 2], df);
            oA1[s] = fmaxf(fmaf(df, dtA, dA2[s + 1]), 0.0f);
            // batch B, x-row 0
            df = wmm[0][s] * dB0[s];
            df = fmaf(wm0[0][s], dB0[s + 1], df);
            df = fmaf(wmp[0][s], dB0[s + 2], df);
            df = fmaf(w0m[0][s], dB1[s],     df);
            df = fmaf(w00[0][s], dB1[s + 1], df);
            df = fmaf(w0p[0][s], dB1[s + 2], df);
            df = fmaf(wpm[0][s], dB2[s],     df);
            df = fmaf(wp0[0][s], dB2[s + 1], df);
            df = fmaf(wpp[0][s], dB2[s + 2], df);
            oB0[s] = fmaxf(fmaf(df, dtB, dB1[s + 1]), 0.0f);
            // batch B, x-row 1
            df = wmm[1][s] * dB1[s];
            df = fmaf(wm0[1][s], dB1[s + 1], df);
            df = fmaf(wmp[1][s], dB1[s + 2], df);
            df = fmaf(w0m[1][s], dB2[s],     df);
            df = fmaf(w00[1][s], dB2[s + 1], df);
            df = fmaf(w0p[1][s], dB2[s + 2], df);
            df = fmaf(wpm[1][s], dB3[s],     df);
            df = fmaf(wp0[1][s], dB3[s + 1], df);
            df = fmaf(wpp[1][s], dB3[s + 2], df);
            oB1[s] = fmaxf(fmaf(df, dtB, dB2[s + 1]), 0.0f);
        }
        *(float4*)O1A         = make_float4(oA0[0], oA0[1], oA0[2], oA0[3]);
        *(float4*)(O1A + NYD) = make_float4(oA1[0], oA1[1], oA1[2], oA1[3]);
        *(float4*)O1B         = make_float4(oB0[0], oB0[1], oB0[2], oB0[3]);
        *(float4*)(O1B + NYD) = make_float4(oB1[0], oB1[1], oB1[2], oB1[3]);
    }
}

extern "C" void kernel_launch(void* const* d_in, const int* in_sizes, int n_in,
                              void* d_out, int out_size) {
    const float* f  = (const float*)d_in[0];
    const float* Ag = (const float*)d_in[1];
    const float* Bg = (const float*)d_in[2];
    const float* dt = (const float*)d_in[3];
    float* out = (float*)d_out;

    fp2d_fused<<<NB_BLK + NI_BLK, 128>>>(f, Ag, Bg, dt, out);
}

// round 14
// speedup vs baseline: 1.2911x; 1.1098x over previous
#include <cuda_runtime.h>

#define NXD 1024
#define NYD 1024
#define BD  16
#define NP  (NXD * NYD)

// boundary: y in {0..3,1020..1023} all x (8192) + x in {0,1023}, y in [4,1019] (2032)
#define NBPTS   10224
#define NB_BLK  80                    // ceil(10224/128); each thread loops 16 batches
#define NI_BLK  1024                  // 8 quad-col groups x 128 x-pair groups

// ---- generic stencil helpers (boundary path) ----
__device__ __forceinline__ void gcoef1(int i, int N, int idx[3], float c[3], int& n) {
    if (i == 0)          { idx[0]=0;   idx[1]=1;   idx[2]=2;   c[0]=-1.5f; c[1]= 2.0f; c[2]=-0.5f; n=3; }
    else if (i == N - 1) { idx[0]=N-1; idx[1]=N-2; idx[2]=N-3; c[0]= 1.5f; c[1]=-2.0f; c[2]= 0.5f; n=3; }
    else                 { idx[0]=i-1; idx[1]=i+1; c[0]=-0.5f; c[1]=0.5f; n=2; }
}

__device__ __forceinline__ void gcoef2(int i, int N, int idx[4], float c[4], int& n) {
    if (i == 0)          { idx[0]=0;   idx[1]=1;   idx[2]=2;   idx[3]=3;   c[0]=2.0f; c[1]=-5.0f; c[2]=4.0f; c[3]=-1.0f; n=4; }
    else if (i == N - 1) { idx[0]=N-1; idx[1]=N-2; idx[2]=N-3; idx[3]=N-4; c[0]=2.0f; c[1]=-5.0f; c[2]=4.0f; c[3]=-1.0f; n=4; }
    else                 { idx[0]=i-1; idx[1]=i;   idx[2]=i+1; c[0]=1.0f; c[1]=-2.0f; c[2]=1.0f; n=3; }
}

__device__ __noinline__ float generic_df(const float* __restrict__ Fb,
                            const float* __restrict__ A0, const float* __restrict__ A1,
                            const float* __restrict__ B0, const float* __restrict__ B1,
                            const float* __restrict__ B2, int x, int y)
{
    int ix1[3]; float cx1[3]; int nx1;
    int iy1[3]; float cy1[3]; int ny1;
    gcoef1(x, NXD, ix1, cx1, nx1);
    gcoef1(y, NYD, iy1, cy1, ny1);

    int ix2[4]; float cx2[4]; int nx2;
    int iy2[4]; float cy2[4]; int ny2;
    gcoef2(x, NXD, ix2, cx2, nx2);
    gcoef2(y, NYD, iy2, cy2, ny2);

    float ga = 0.0f;
    #pragma unroll
    for (int j = 0; j < 3; ++j)
        if (j < nx1) { int k = ix1[j] * NYD + y; ga += cx1[j] * __ldg(&A0[k]) * __ldg(&Fb[k]); }
    #pragma unroll
    for (int j = 0; j < 3; ++j)
        if (j < ny1) { int k = x * NYD + iy1[j]; ga += cy1[j] * __ldg(&A1[k]) * __ldg(&Fb[k]); }

    float gb = 0.0f;
    #pragma unroll
    for (int j = 0; j < 4; ++j)
        if (j < nx2) { int k = ix2[j] * NYD + y; gb += cx2[j] * __ldg(&B0[k]) * __ldg(&Fb[k]); }
    #pragma unroll
    for (int j = 0; j < 4; ++j)
        if (j < ny2) { int k = x * NYD + iy2[j]; gb += cy2[j] * __ldg(&B1[k]) * __ldg(&Fb[k]); }

    float gc = 0.0f;
    #pragma unroll
    for (int j = 0; j < 3; ++j)
        if (j < nx1) {
            float acc = 0.0f;
            #pragma unroll
            for (int k = 0; k < 3; ++k)
                if (k < ny1) {
                    int idx = ix1[j] * NYD + iy1[k];
                    acc += cy1[k] * __ldg(&B2[idx]) * __ldg(&Fb[idx]);
                }
            gc += cx1[j] * acc;
        }
    return -ga + 0.5f * gb + gc;
}

// 6-value row [base-1 .. base+4], base % 4 == 0, lane stride 16B
__device__ __forceinline__ void load_row6(const float* __restrict__ P, int base, float d[6]) {
    float2 e0 = __ldg((const float2*)&P[base - 2]);
    float4 m  = __ldg((const float4*)&P[base]);
    float2 e1 = __ldg((const float2*)&P[base + 4]);
    d[0]=e0.y; d[1]=m.x; d[2]=m.y; d[3]=m.z; d[4]=m.w; d[5]=e1.x;
}

// compute the 2x4 patch from rows r0..r3 and store both output rows
#define PATCH_STORE(r0, r1, r2, r3, dtb, Optr) do {                        \
    float o0[4], o1[4];                                                    \
    _Pragma("unroll")                                                      \
    for (int s = 0; s < 4; ++s) {                                          \
        float df;                                                          \
        df = wmm[0][s] * r0[s];                                            \
        df = fmaf(wm0[0][s], r0[s + 1], df);                               \
        df = fmaf(wmp[0][s], r0[s + 2], df);                               \
        df = fmaf(w0m[0][s], r1[s],     df);                               \
        df = fmaf(w00[0][s], r1[s + 1], df);                               \
        df = fmaf(w0p[0][s], r1[s + 2], df);                               \
        df = fmaf(wpm[0][s], r2[s],     df);                               \
        df = fmaf(wp0[0][s], r2[s + 1], df);                               \
        df = fmaf(wpp[0][s], r2[s + 2], df);                               \
        o0[s] = fmaxf(fmaf(df, dtb, r1[s + 1]), 0.0f);                     \
        df = wmm[1][s] * r1[s];                                            \
        df = fmaf(wm0[1][s], r1[s + 1], df);                               \
        df = fmaf(wmp[1][s], r1[s + 2], df);                               \
        df = fmaf(w0m[1][s], r2[s],     df);                               \
        df = fmaf(w00[1][s], r2[s + 1], df);                               \
        df = fmaf(w0p[1][s], r2[s + 2], df);                               \
        df = fmaf(wpm[1][s], r3[s],     df);                               \
        df = fmaf(wp0[1][s], r3[s + 1], df);                               \
        df = fmaf(wpp[1][s], r3[s + 2], df);                               \
        o1[s] = fmaxf(fmaf(df, dtb, r2[s + 1]), 0.0f);                     \
    }                                                                      \
    *(float4*)(Optr)         = make_float4(o0[0], o0[1], o0[2], o0[3]);    \
    *(float4*)((Optr) + NYD) = make_float4(o1[0], o1[1], o1[2], o1[3]);    \
} while (0)

// ================= fused kernel =================
// blocks [0, NB_BLK)             : boundary points (each thread loops 16 batches)
// blocks [NB_BLK, NB_BLK+NI_BLK) : interior, 2x-rows x 4y patch, 3 batch streams
__global__ void __launch_bounds__(128, 3) fp2d_fused(
    const float* __restrict__ f,      // [B, NX, NY]
    const float* __restrict__ Agrid,  // [2, NX, NY]
    const float* __restrict__ Bgrid,  // [3, NX, NY]
    const float* __restrict__ dt,     // [B]
    float* __restrict__ out)          // [B, NX, NY]
{
    const float* __restrict__ A0 = Agrid;
    const float* __restrict__ A1 = Agrid + NP;
    const float* __restrict__ B0 = Bgrid;
    const float* __restrict__ B1 = Bgrid + NP;
    const float* __restrict__ B2 = Bgrid + 2 * NP;

    const int bid = blockIdx.x;

    if (bid < NB_BLK) {
        // ---------------- boundary path: one point, 16 batches ----------------
        const int idx = bid * 128 + threadIdx.x;
        if (idx >= NBPTS) return;
        int x, y;
        if (idx < 8192) {
            x = idx >> 3;
            int r = idx & 7;
            y = (r < 4) ? r : (1016 + r);
        } else {
            int r = idx - 8192;
            x = (r & 1) ? 1023 : 0;
            y = 4 + (r >> 1);
        }
        const int k = x * NYD + y;
        const float* __restrict__ Fb = f;
        float* __restrict__ Ob = out + k;
        for (int b = 0; b < BD; ++b, Fb += NP, Ob += NP) {
            const float df = generic_df(Fb, A0, A1, B0, B1, B2, x, y);
            float v = fmaf(df, __ldg(&dt[b]), __ldg(&Fb[k]));
            *Ob = fmaxf(v, 0.0f);
        }
        return;
    }

    // ---------------- interior path ----------------
    const int ib = bid - NB_BLK;
    const int bx = ib & 7;                    // 0..7   quad-column group
    const int by = ib >> 3;                   // 0..127 x-pair group
    const int q  = 1 + bx * 32 + (threadIdx.x & 31);   // quad index, want [1,254]
    const int p  = by * 4 + (threadIdx.x >> 5);        // x-pair index, want [0,510]
    if (q > 254 || p > 510) return;
    const int x0 = 1 + 2 * p;                 // rows x0, x0+1
    const int y0 = q * 4;

    const int b0_ = (x0 - 1) * NYD + y0;
    const int b1_ =  x0      * NYD + y0;
    const int b2_ = (x0 + 1) * NYD + y0;
    const int b3_ = (x0 + 2) * NYD + y0;

    // ---- batch-invariant grid rows ----
    float b2r0[6], b2r1[6], b2r2[6], b2r3[6], a1r1[6], a1r2[6], b1r1[6], b1r2[6];
    load_row6(B2, b0_, b2r0);
    load_row6(B2, b1_, b2r1);
    load_row6(B2, b2_, b2r2);
    load_row6(B2, b3_, b2r3);
    load_row6(A1, b1_, a1r1);
    load_row6(A1, b2_, a1r2);
    load_row6(B1, b1_, b1r1);
    load_row6(B1, b2_, b1r2);

    const float4 a0r0 = __ldg((const float4*)&A0[b0_]);
    const float4 a0r1 = __ldg((const float4*)&A0[b1_]);
    const float4 a0r2 = __ldg((const float4*)&A0[b2_]);
    const float4 a0r3 = __ldg((const float4*)&A0[b3_]);
    const float4 b0r0 = __ldg((const float4*)&B0[b0_]);
    const float4 b0r1 = __ldg((const float4*)&B0[b1_]);
    const float4 b0r2 = __ldg((const float4*)&B0[b2_]);
    const float4 b0r3 = __ldg((const float4*)&B0[b3_]);

    // ---- fold into 9 weights per point, 2 x-rows ----
    float wmm[2][4], wm0[2][4], wmp[2][4], w0m[2][4], w00[2][4], w0p[2][4],
          wpm[2][4], wp0[2][4], wpp[2][4];
    {
        const float a0m_[2][4] = {{a0r0.x,a0r0.y,a0r0.z,a0r0.w},{a0r1.x,a0r1.y,a0r1.z,a0r1.w}};
        const float a0p_[2][4] = {{a0r2.x,a0r2.y,a0r2.z,a0r2.w},{a0r3.x,a0r3.y,a0r3.z,a0r3.w}};
        const float b0m_[2][4] = {{b0r0.x,b0r0.y,b0r0.z,b0r0.w},{b0r1.x,b0r1.y,b0r1.z,b0r1.w}};
        const float b0c_[2][4] = {{b0r1.x,b0r1.y,b0r1.z,b0r1.w},{b0r2.x,b0r2.y,b0r2.z,b0r2.w}};
        const float b0p_[2][4] = {{b0r2.x,b0r2.y,b0r2.z,b0r2.w},{b0r3.x,b0r3.y,b0r3.z,b0r3.w}};
        const float* b2m_[2] = {b2r0, b2r1};
        const float* b2p_[2] = {b2r2, b2r3};
        const float* a1c_[2] = {a1r1, a1r2};
        const float* b1c_[2] = {b1r1, b1r2};
        #pragma unroll
        for (int r = 0; r < 2; ++r) {
            #pragma unroll
            for (int s = 0; s < 4; ++s) {
                wmm[r][s] =  0.25f * b2m_[r][s];
                wmp[r][s] = -0.25f * b2m_[r][s + 2];
                wpm[r][s] = -0.25f * b2p_[r][s];
                wpp[r][s] =  0.25f * b2p_[r][s + 2];
                w0m[r][s] =  0.5f * (a1c_[r][s] + b1c_[r][s]);
                w0p[r][s] =  0.5f * (b1c_[r][s + 2] - a1c_[r][s + 2]);
                wm0[r][s] =  0.5f * (a0m_[r][s] + b0m_[r][s]);
                wp0[r][s] =  0.5f * (b0p_[r][s] - a0p_[r][s]);
                w00[r][s] = -(b0c_[r][s] + b1c_[r][s + 1]);
            }
        }
    }

    // ---- batch loop: 3 independent streams {i, i+5, i+10}, 5 iters -> batches 0..14 ----
    #pragma unroll 1
    for (int i = 0; i < 5; ++i) {
        const float* __restrict__ FA = f + i * NP;
        const float* __restrict__ FB = f + (i + 5) * NP;
        const float* __restrict__ FC = f + (i + 10) * NP;
        const float dtA = __ldg(&dt[i]);
        const float dtB = __ldg(&dt[i + 5]);
        const float dtC = __ldg(&dt[i + 10]);

        float dA0[6], dA1[6], dA2[6], dA3[6];
        float dB0[6], dB1[6], dB2[6], dB3[6];
        float dC0[6], dC1[6], dC2[6], dC3[6];
        load_row6(FA, b0_, dA0);
        load_row6(FA, b1_, dA1);
        load_row6(FA, b2_, dA2);
        load_row6(FA, b3_, dA3);
        load_row6(FB, b0_, dB0);
        load_row6(FB, b1_, dB1);
        load_row6(FB, b2_, dB2);
        load_row6(FB, b3_, dB3);
        load_row6(FC, b0_, dC0);
        load_row6(FC, b1_, dC1);
        load_row6(FC, b2_, dC2);
        load_row6(FC, b3_, dC3);

        PATCH_STORE(dA0, dA1, dA2, dA3, dtA, out + b1_ + i * NP);
        PATCH_STORE(dB0, dB1, dB2, dB3, dtB, out + b1_ + (i + 5) * NP);
        PATCH_STORE(dC0, dC1, dC2, dC3, dtC, out + b1_ + (i + 10) * NP);
    }

    // ---- remainder: batch 15 ----
    {
        const float* __restrict__ FA = f + 15 * NP;
        const float dtA = __ldg(&dt[15]);
        float dA0[6], dA1[6], dA2[6], dA3[6];
        load_row6(FA, b0_, dA0);
        load_row6(FA, b1_, dA1);
        load_row6(FA, b2_, dA2);
        load_row6(FA, b3_, dA3);
        PATCH_STORE(dA0, dA1, dA2, dA3, dtA, out + b1_ + 15 * NP);
    }
}

extern "C" void kernel_launch(void* const* d_in, const int* in_sizes, int n_in,
                              void* d_out, int out_size) {
    const float* f  = (const float*)d_in[0];
    const float* Ag = (const float*)d_in[1];
    const float* Bg = (const float*)d_in[2];
    const float* dt = (const float*)d_in[3];
    float* out = (float*)d_out;

    fp2d_fused<<<NB_BLK + NI_BLK, 128>>>(f, Ag, Bg, dt, out);
}